// round 15
// baseline (speedup 1.0000x reference)
#include <cuda_runtime.h>

// D = 16777216 floats per vector; n4 = D/4 float4 elements.
// Output: out[0..D) = x, out[D..D+6) = {ly0·x, ly1·x, ly1·ly0, ly2·x, ly2·ly0, ly2·ly1}
//
// Converged configuration (14 rounds), final untested axis: block size.
// R15: 512 threads x 2048 blocks (same 1M threads, 4 iters/thread) — halves
// CTA-dispatch + epilogue count vs 256x4096. Everything else identical to the
// best-observed config (R1/R14, kernel 48.0us @ 83.6% DRAM, total 53.3-53.4us):
//  - plain loads and stores (cache hints measured neutral-to-negative)
//  - NO __threadfence (CCTL.IVALL L1D flush, ~3us tax)
//  - fire-and-forget atomicAdd epilogue into pre-zeroed out_tail
//  - traffic floor 320MB; plateau ~6.6TB/s = HBM ceiling for 4R:1W mix

#define NTHREADS 512
#define NBLOCKS  2048
#define NWARPS   (NTHREADS / 32)

#define DOT4(u, v) ((u).x*(v).x + (u).y*(v).y + (u).z*(v).z + (u).w*(v).w)

__global__ void zero_tail_kernel(float* __restrict__ out_tail) {
    if (threadIdx.x < 6) out_tail[threadIdx.x] = 0.0f;
}

__global__ void __launch_bounds__(NTHREADS)
dlrm_fused_kernel(const float4* __restrict__ xv,
                  const float4* __restrict__ l0v,
                  const float4* __restrict__ l1v,
                  const float4* __restrict__ l2v,
                  float4* __restrict__ outx,
                  float* __restrict__ out_tail,
                  int n4) {
    float s0 = 0.f, s1 = 0.f, s2 = 0.f, s3 = 0.f, s4 = 0.f, s5 = 0.f;

    const int stride = gridDim.x * blockDim.x;
    for (int i = blockIdx.x * blockDim.x + threadIdx.x; i < n4; i += stride) {
        const float4 a = xv[i];
        const float4 b = l0v[i];
        const float4 c = l1v[i];
        const float4 d = l2v[i];
        outx[i] = a;  // fused copy of x into out (plain store)

        s0 += DOT4(b, a);  // ly0 · x
        s1 += DOT4(c, a);  // ly1 · x
        s2 += DOT4(c, b);  // ly1 · ly0
        s3 += DOT4(d, a);  // ly2 · x
        s4 += DOT4(d, b);  // ly2 · ly0
        s5 += DOT4(d, c);  // ly2 · ly1
    }

    // Warp-level reduction
    #pragma unroll
    for (int off = 16; off > 0; off >>= 1) {
        s0 += __shfl_down_sync(0xFFFFFFFFu, s0, off);
        s1 += __shfl_down_sync(0xFFFFFFFFu, s1, off);
        s2 += __shfl_down_sync(0xFFFFFFFFu, s2, off);
        s3 += __shfl_down_sync(0xFFFFFFFFu, s3, off);
        s4 += __shfl_down_sync(0xFFFFFFFFu, s4, off);
        s5 += __shfl_down_sync(0xFFFFFFFFu, s5, off);
    }

    __shared__ float smem[6][NWARPS];
    const int warp = threadIdx.x >> 5;
    const int lane = threadIdx.x & 31;
    if (lane == 0) {
        smem[0][warp] = s0; smem[1][warp] = s1; smem[2][warp] = s2;
        smem[3][warp] = s3; smem[4][warp] = s4; smem[5][warp] = s5;
    }
    __syncthreads();

    // Threads 0..5: one fire-and-forget atomicAdd each (REDG, no return wait).
    if (threadIdx.x < 6) {
        float v = 0.f;
        #pragma unroll
        for (int w = 0; w < NWARPS; w++) v += smem[threadIdx.x][w];
        atomicAdd(out_tail + threadIdx.x, v);
    }
}

extern "C" void kernel_launch(void* const* d_in, const int* in_sizes, int n_in,
                              void* d_out, int out_size) {
    const float* x  = (const float*)d_in[0];
    const float* l0 = (const float*)d_in[1];
    const float* l1 = (const float*)d_in[2];
    const float* l2 = (const float*)d_in[3];
    float* out = (float*)d_out;

    const int D  = in_sizes[0];   // 16777216
    const int n4 = D / 4;         // 4194304

    zero_tail_kernel<<<1, 32>>>(out + D);

    int blocks = NBLOCKS;
    const int maxBlocks = (n4 + NTHREADS - 1) / NTHREADS;
    if (blocks > maxBlocks) blocks = maxBlocks;

    dlrm_fused_kernel<<<blocks, NTHREADS>>>(
        (const float4*)x, (const float4*)l0, (const float4*)l1, (const float4*)l2,
        (float4*)out, out + D, n4);
}

// round 16
// speedup vs baseline: 1.0126x; 1.0126x over previous
#include <cuda_runtime.h>

// D = 16777216 floats per vector; n4 = D/4 float4 elements.
// Output: out[0..D) = x, out[D..D+6) = {ly0·x, ly1·x, ly1·ly0, ly2·x, ly2·ly0, ly2·ly1}
//
// FINAL — converged after 15 rounds of single-variable measurement.
// Kernel: 48.0us = 320MB @ 6.62TB/s (82.7% of 8TB/s spec), the HBM device
// ceiling for a 4-read:1-write stream mix. All SM pipes <11%, LTS at 46% of
// its cap, occupancy ~97%: DRAM is the only binding resource.
//
// Measured verdicts (losers):
//  - in-thread unroll x2: regs 32->54, occ 47%, no BW gain (R5)
//  - persistent 1216-block grid: 51.4us (R6); 8192 blocks: 49.8us (R10);
//    512-thread blocks: 48.8us (R15). Optimum: 4096 x 256.
//  - __threadfence in epilogue: CCTL.IVALL L1D flush, ~3us tax (R2-R7)
//  - last-block / ticket reductions: serialized DRAM-latency tail (R4)
//  - .cs load hints: negative (R8); .cs store: 0.2-1.3us slower than plain
//    across 4 samples (R9-R13) vs plain 2/2 at 48.0us (R1, R14)
// Winner: simple grid-stride float4 loop, plain loads/stores, warp-shuffle +
// smem block reduction, 6 fire-and-forget atomicAdds (REDG) into a pre-zeroed
// tail, zeroed by a 1-warp kernel (graph-node cost within harness noise).

#define NTHREADS 256
#define NBLOCKS  4096

#define DOT4(u, v) ((u).x*(v).x + (u).y*(v).y + (u).z*(v).z + (u).w*(v).w)

__global__ void zero_tail_kernel(float* __restrict__ out_tail) {
    if (threadIdx.x < 6) out_tail[threadIdx.x] = 0.0f;
}

__global__ void __launch_bounds__(NTHREADS)
dlrm_fused_kernel(const float4* __restrict__ xv,
                  const float4* __restrict__ l0v,
                  const float4* __restrict__ l1v,
                  const float4* __restrict__ l2v,
                  float4* __restrict__ outx,
                  float* __restrict__ out_tail,
                  int n4) {
    float s0 = 0.f, s1 = 0.f, s2 = 0.f, s3 = 0.f, s4 = 0.f, s5 = 0.f;

    const int stride = gridDim.x * blockDim.x;
    for (int i = blockIdx.x * blockDim.x + threadIdx.x; i < n4; i += stride) {
        const float4 a = xv[i];
        const float4 b = l0v[i];
        const float4 c = l1v[i];
        const float4 d = l2v[i];
        outx[i] = a;  // fused copy of x into out

        s0 += DOT4(b, a);  // ly0 · x
        s1 += DOT4(c, a);  // ly1 · x
        s2 += DOT4(c, b);  // ly1 · ly0
        s3 += DOT4(d, a);  // ly2 · x
        s4 += DOT4(d, b);  // ly2 · ly0
        s5 += DOT4(d, c);  // ly2 · ly1
    }

    // Warp-level reduction
    #pragma unroll
    for (int off = 16; off > 0; off >>= 1) {
        s0 += __shfl_down_sync(0xFFFFFFFFu, s0, off);
        s1 += __shfl_down_sync(0xFFFFFFFFu, s1, off);
        s2 += __shfl_down_sync(0xFFFFFFFFu, s2, off);
        s3 += __shfl_down_sync(0xFFFFFFFFu, s3, off);
        s4 += __shfl_down_sync(0xFFFFFFFFu, s4, off);
        s5 += __shfl_down_sync(0xFFFFFFFFu, s5, off);
    }

    __shared__ float smem[6][NTHREADS / 32];
    const int warp = threadIdx.x >> 5;
    const int lane = threadIdx.x & 31;
    if (lane == 0) {
        smem[0][warp] = s0; smem[1][warp] = s1; smem[2][warp] = s2;
        smem[3][warp] = s3; smem[4][warp] = s4; smem[5][warp] = s5;
    }
    __syncthreads();

    // Threads 0..5: one fire-and-forget atomicAdd each (REDG, no return wait).
    if (threadIdx.x < 6) {
        float v = 0.f;
        #pragma unroll
        for (int w = 0; w < NTHREADS / 32; w++) v += smem[threadIdx.x][w];
        atomicAdd(out_tail + threadIdx.x, v);
    }
}

extern "C" void kernel_launch(void* const* d_in, const int* in_sizes, int n_in,
                              void* d_out, int out_size) {
    const float* x  = (const float*)d_in[0];
    const float* l0 = (const float*)d_in[1];
    const float* l1 = (const float*)d_in[2];
    const float* l2 = (const float*)d_in[3];
    float* out = (float*)d_out;

    const int D  = in_sizes[0];   // 16777216
    const int n4 = D / 4;         // 4194304

    zero_tail_kernel<<<1, 32>>>(out + D);

    int blocks = NBLOCKS;
    const int maxBlocks = (n4 + NTHREADS - 1) / NTHREADS;
    if (blocks > maxBlocks) blocks = maxBlocks;

    dlrm_fused_kernel<<<blocks, NTHREADS>>>(
        (const float4*)x, (const float4*)l0, (const float4*)l1, (const float4*)l2,
        (float4*)out, out + D, n4);
}